// round 1
// baseline (speedup 1.0000x reference)
#include <cuda_runtime.h>
#include <math.h>
#include <stdint.h>

#define KK 128
#define DD 64
#define BM 128
#define PADX 65                 // ull (float2) stride per sX row
#define LOG2PI 1.8378770664093454835

typedef unsigned long long ull;

__device__ ull    g_wcomb[DD * KK];   // packed (w2=-0.5*nb, w1=tau*nb), [d][k]
__device__ float  g_A[KK];
__device__ double g_kl;
__device__ double g_ll;

// ---------------------------------------------------------------- helpers
__device__ __forceinline__ ull pack2(float lo, float hi) {
    return (ull)__float_as_uint(lo) | ((ull)__float_as_uint(hi) << 32);
}

__device__ __forceinline__ void ffma2(ull& acc, ull a, ull b) {
    asm("fma.rn.f32x2 %0, %1, %2, %3;" : "=l"(acc) : "l"(a), "l"(b), "l"(acc));
}

__device__ double dg(double x) {   // digamma, double precision
    double s = 0.0;
    while (x < 8.0) { s -= 1.0 / x; x += 1.0; }
    double inv = 1.0 / x, i2 = inv * inv;
    double r = log(x) - 0.5 * inv
        - i2 * (1.0/12.0 - i2 * (1.0/120.0 - i2 * (1.0/252.0
          - i2 * (1.0/240.0 - i2 * (1.0/132.0)))));
    return r + s;
}

// ---------------------------------------------------------------- setup
__global__ void setup_kernel(const float* __restrict__ nu, const float* __restrict__ nv,
                             const float* __restrict__ ntau, const float* __restrict__ nc,
                             const float* __restrict__ nn, const float* __restrict__ nB) {
    __shared__ double sh[KK];
    __shared__ double pre[KK];
    __shared__ double red[KK];
    int k = threadIdx.x;

    double u = (double)nu[k] + 1.0;
    double v = (double)nv[k] + 1.0;
    double c = (double)nc[k];
    double n = (double)nn[k] - (double)DD - 2.0;

    double a1   = 0.5 * n;
    double dga1 = dg(a1);
    double lga1 = lgamma(a1);
    double a0g  = 0.5 * ((double)DD + 2.0);  // N0/2
    double b0g  = 0.5;                       // B0/2
    double lga0g = lgamma(a0g);

    double sum_log_halfB = 0.0, sum_t2nb = 0.0, klg = 0.0, kln = 0.0;
    for (int d = 0; d < DD; d++) {
        double t  = (double)ntau[k * DD + d] / c;
        double B  = (double)nB[k * DD + d] - c * t * t;
        double nbv = n / B;
        float w2 = (float)(-0.5 * nbv);
        float w1 = (float)(t * nbv);
        g_wcomb[d * KK + k] = pack2(w2, w1);
        sum_log_halfB += log(0.5 * B);
        sum_t2nb      += t * t * nbv;
        double b1 = 0.5 * B;
        klg += (a1 - a0g) * dga1 - lga1 + lga0g
             + a0g * (log(b1) - log(b0g)) + a1 * (b0g - b1) / b1;
        kln += 0.5 * (log(c) + 1.0 / c - 1.0 + nbv * t * t);  // C0=1, TAU0=0
    }
    double e_log_det = (double)DD * dga1 - sum_log_halfB;

    double dguv  = dg(u + v);
    double e_stick = dg(u) - dguv;
    double e_1m    = dg(v) - dguv;
    sh[k] = e_1m;

    // KL(Beta(u,v) || Beta(1, 1)) (ALPHA_DP = 1)
    double klb = lgamma(u + v) - lgamma(u) - lgamma(v)
               - (lgamma(2.0) - lgamma(1.0) - lgamma(1.0))
               + (u - 1.0) * dg(u) + (v - 1.0) * dg(v)
               + (2.0 - u - v) * dguv;

    __syncthreads();
    if (k == 0) {
        double acc = 0.0;
        for (int j = 0; j < KK; j++) { pre[j] = acc; acc += sh[j]; }
    }
    __syncthreads();

    double e_log_pi = e_stick + pre[k];
    g_A[k] = (float)(e_log_pi + 0.5 * (e_log_det - (double)DD * LOG2PI
                                       - sum_t2nb - (double)DD / c));
    red[k] = klb + klg + kln;
    __syncthreads();
    for (int off = KK / 2; off > 0; off >>= 1) {
        if (k < off) red[k] += red[k + off];
        __syncthreads();
    }
    if (k == 0) { g_kl = red[0]; g_ll = 0.0; }
}

// ---------------------------------------------------------------- main GEMM+softmax
__global__ void __launch_bounds__(256, 1)
main_kernel(const float* __restrict__ x, float* __restrict__ out) {
    extern __shared__ ull smem[];
    ull*    sW  = smem;                        // [DD][KK] packed weights
    ull*    sX  = smem + DD * KK;              // [BM][PADX] packed (x^2, x)
    float*  sA  = (float*)(smem + DD * KK + BM * PADX);
    double* dll = (double*)(sA + KK);

    int tid = threadIdx.x;
    int tx = tid & 15, ty = tid >> 4;
    int rowbase = blockIdx.x * BM;

    // stage weights + A
    #pragma unroll
    for (int i = tid; i < DD * KK; i += 256) sW[i] = g_wcomb[i];
    if (tid < KK) sA[tid] = g_A[tid];

    // stage x tile, packing (x^2, x), transposed-free [row][d] layout
    const float4* xg = (const float4*)(x + (size_t)rowbase * DD);
    #pragma unroll
    for (int p = 0; p < 8; p++) {
        int q = tid + 256 * p;            // 2048 float4 per tile
        int r = q >> 4, d4 = (q & 15) << 2;
        float4 vv = xg[q];
        ull* dst = sX + r * PADX + d4;
        dst[0] = pack2(vv.x * vv.x, vv.x);
        dst[1] = pack2(vv.y * vv.y, vv.y);
        dst[2] = pack2(vv.z * vv.z, vv.z);
        dst[3] = pack2(vv.w * vv.w, vv.w);
    }
    __syncthreads();

    ull acc[8][8];
    #pragma unroll
    for (int i = 0; i < 8; i++)
        #pragma unroll
        for (int j = 0; j < 8; j++) acc[i][j] = 0ULL;

    const ull* xrow = sX + (ty * 8) * PADX;
    #pragma unroll 4
    for (int kk = 0; kk < DD; kk++) {
        ull xv[8], wv[8];
        #pragma unroll
        for (int i = 0; i < 8; i++) xv[i] = xrow[i * PADX + kk];
        const ull* wrow = sW + kk * KK + tx;
        #pragma unroll
        for (int j = 0; j < 8; j++) wv[j] = wrow[j * 16];
        #pragma unroll
        for (int i = 0; i < 8; i++)
            #pragma unroll
            for (int j = 0; j < 8; j++)
                ffma2(acc[i][j], wv[j], xv[i]);
    }

    // fused softmax epilogue: row owned by the 16 lanes sharing (lane>>4)
    double llacc = 0.0;
    #pragma unroll
    for (int i = 0; i < 8; i++) {
        int row = ty * 8 + i;
        float lg[8];
        float m = -3.402823466e+38f;
        #pragma unroll
        for (int j = 0; j < 8; j++) {
            ull a = acc[i][j];
            float lo = __uint_as_float((unsigned)a);
            float hi = __uint_as_float((unsigned)(a >> 32));
            lg[j] = lo + hi + sA[tx + 16 * j];
            m = fmaxf(m, lg[j]);
        }
        #pragma unroll
        for (int o = 8; o > 0; o >>= 1)
            m = fmaxf(m, __shfl_xor_sync(0xffffffffu, m, o));
        float s = 0.f;
        #pragma unroll
        for (int j = 0; j < 8; j++) { lg[j] = __expf(lg[j] - m); s += lg[j]; }
        #pragma unroll
        for (int o = 8; o > 0; o >>= 1)
            s += __shfl_xor_sync(0xffffffffu, s, o);
        float inv = 1.0f / s;
        float* orow = out + (size_t)(rowbase + row) * KK;
        #pragma unroll
        for (int j = 0; j < 8; j++) orow[tx + 16 * j] = lg[j] * inv;
        if (tx == 0) llacc += (double)(m + logf(s));
    }

    if ((tid & 15) == 0) dll[tid >> 4] = llacc;
    __syncthreads();
    if (tid == 0) {
        double t = 0.0;
        #pragma unroll
        for (int i = 0; i < 16; i++) t += dll[i];
        atomicAdd(&g_ll, t);
    }
}

// ---------------------------------------------------------------- finalize
__global__ void fin_kernel(float* out, long long idx) {
    out[idx] = (float)(g_kl - g_ll);
}

// ---------------------------------------------------------------- launch
extern "C" void kernel_launch(void* const* d_in, const int* in_sizes, int n_in,
                              void* d_out, int out_size) {
    const float* x    = (const float*)d_in[0];
    const float* nu   = (const float*)d_in[1];
    const float* nv   = (const float*)d_in[2];
    const float* ntau = (const float*)d_in[3];
    const float* nc   = (const float*)d_in[4];
    const float* nn   = (const float*)d_in[5];
    const float* nB   = (const float*)d_in[6];

    int K = in_sizes[1];
    int D = in_sizes[3] / K;
    int N = in_sizes[0] / D;

    size_t smbytes = (size_t)(DD * KK + BM * PADX) * 8 + KK * 4 + 16 * 8;
    cudaFuncSetAttribute(main_kernel, cudaFuncAttributeMaxDynamicSharedMemorySize,
                         (int)smbytes);

    setup_kernel<<<1, KK>>>(nu, nv, ntau, nc, nn, nB);
    main_kernel<<<N / BM, 256, smbytes>>>(x, (float*)d_out);
    fin_kernel<<<1, 1>>>((float*)d_out, (long long)out_size - 1);
}

// round 2
// speedup vs baseline: 2.0046x; 2.0046x over previous
#include <cuda_runtime.h>
#include <math.h>
#include <stdint.h>

#define KK 128
#define DD 64
#define BM 128
#define PADX 66                 // ull stride per sX row (even -> 16B-aligned pairs)
#define LOG2PI 1.8378770664093454835
#define GRID_MAIN 512

typedef unsigned long long ull;

// weights packed (w2=-0.5*nb, w1=tau*nb), pair layout [kp=d/2][k][d&1]
__device__ ull    g_wcomb[DD * KK];
__device__ float  g_A[KK];
__device__ double g_kl;
__device__ double g_ll;
__device__ double g_estick[KK], g_e1m[KK], g_base[KK], g_klk[KK];

// ---------------------------------------------------------------- helpers
__device__ __forceinline__ ull pack2(float lo, float hi) {
    return (ull)__float_as_uint(lo) | ((ull)__float_as_uint(hi) << 32);
}

__device__ __forceinline__ void ffma2(ull& acc, ull a, ull b) {
    asm("fma.rn.f32x2 %0, %1, %2, %3;" : "=l"(acc) : "l"(a), "l"(b), "l"(acc));
}

__device__ double dg(double x) {   // digamma, double precision
    double s = 0.0;
    while (x < 8.0) { s -= 1.0 / x; x += 1.0; }
    double inv = 1.0 / x, i2 = inv * inv;
    double r = log(x) - 0.5 * inv
        - i2 * (1.0/12.0 - i2 * (1.0/120.0 - i2 * (1.0/252.0
          - i2 * (1.0/240.0 - i2 * (1.0/132.0)))));
    return r + s;
}

// ---------------------------------------------------------------- setup, stage 1
// one block per k (128 blocks), one thread per d (64 threads)
__global__ void setup1_kernel(const float* __restrict__ nu, const float* __restrict__ nv,
                              const float* __restrict__ ntau, const float* __restrict__ nc,
                              const float* __restrict__ nn, const float* __restrict__ nB) {
    __shared__ double sred[3][2];
    int k = blockIdx.x, d = threadIdx.x;
    int lane = d & 31, warp = d >> 5;

    double c = (double)nc[k];
    double n = (double)nn[k] - (double)DD - 2.0;

    double t   = (double)ntau[k * DD + d] / c;
    double B   = (double)nB[k * DD + d] - c * t * t;
    double nbv = n / B;
    g_wcomb[(d >> 1) * (2 * KK) + (k << 1) + (d & 1)]
        = pack2((float)(-0.5 * nbv), (float)(t * nbv));

    double logb1 = log(0.5 * B);            // log(B/2)
    double t2nb  = t * t * nbv;
    double rat   = (0.5 - 0.5 * B) / (0.5 * B);   // (b0g - b1)/b1, b0g = 0.5

    #pragma unroll
    for (int off = 16; off > 0; off >>= 1) {
        logb1 += __shfl_down_sync(0xffffffffu, logb1, off);
        t2nb  += __shfl_down_sync(0xffffffffu, t2nb,  off);
        rat   += __shfl_down_sync(0xffffffffu, rat,   off);
    }
    if (lane == 0) { sred[0][warp] = logb1; sred[1][warp] = t2nb; sred[2][warp] = rat; }
    __syncthreads();

    if (d == 0) {
        double SlogB = sred[0][0] + sred[0][1];
        double St2   = sred[1][0] + sred[1][1];
        double Srat  = sred[2][0] + sred[2][1];

        double a1 = 0.5 * n, a0g = 0.5 * ((double)DD + 2.0), b0g = 0.5;
        double dga1 = dg(a1), lga1 = lgamma(a1), lga0g = lgamma(a0g);

        double e_log_det = (double)DD * dga1 - SlogB;
        double klg = (double)DD * ((a1 - a0g) * dga1 - lga1 + lga0g - a0g * log(b0g))
                   + a0g * SlogB + a1 * Srat;
        double kln = 0.5 * ((double)DD * (log(c) + 1.0 / c - 1.0) + St2);

        double u = (double)nu[k] + 1.0, v = (double)nv[k] + 1.0;
        double dgu = dg(u), dgv = dg(v), dguv = dg(u + v);
        double klb = lgamma(u + v) - lgamma(u) - lgamma(v)
                   + (u - 1.0) * dgu + (v - 1.0) * dgv + (2.0 - u - v) * dguv;

        g_estick[k] = dgu - dguv;
        g_e1m[k]    = dgv - dguv;
        g_base[k]   = 0.5 * (e_log_det - (double)DD * LOG2PI - St2 - (double)DD / c);
        g_klk[k]    = klb + klg + kln;
    }
}

// ---------------------------------------------------------------- setup, stage 2
__global__ void setup2_kernel() {
    __shared__ double sh[KK], pre[KK], red[KK];
    int k = threadIdx.x;
    sh[k]  = g_e1m[k];
    red[k] = g_klk[k];
    __syncthreads();
    if (k == 0) {
        double a = 0.0;
        for (int j = 0; j < KK; j++) { pre[j] = a; a += sh[j]; }
    }
    __syncthreads();
    g_A[k] = (float)(g_estick[k] + pre[k] + g_base[k]);
    __syncthreads();
    for (int off = KK / 2; off > 0; off >>= 1) {
        if (k < off) red[k] += red[k + off];
        __syncthreads();
    }
    if (k == 0) { g_kl = red[0]; g_ll = 0.0; }
}

// ---------------------------------------------------------------- main GEMM+softmax
__global__ void __launch_bounds__(256, 1)
main_kernel(const float* __restrict__ x, float* __restrict__ out, int ntiles) {
    extern __shared__ ull smem[];
    ull*    sW  = smem;                        // [32][128][2] packed weight pairs
    ull*    sX  = smem + DD * KK;              // [BM][PADX] packed (x^2, x)
    float*  sA  = (float*)(smem + DD * KK + BM * PADX);
    double* dll = (double*)(sA + KK);

    int tid = threadIdx.x;
    int tx = tid & 15, ty = tid >> 4;

    // stage weights + A once per block
    #pragma unroll
    for (int i = tid; i < DD * KK; i += 256) sW[i] = g_wcomb[i];
    if (tid < KK) sA[tid] = g_A[tid];

    double llacc = 0.0;

    for (int tile = blockIdx.x; tile < ntiles; tile += GRID_MAIN) {
        __syncthreads();   // protect sX (prev iter readers) / sW staging (first iter)

        int rowbase = tile * BM;
        const float4* xg = (const float4*)(x + (size_t)rowbase * DD);
        #pragma unroll
        for (int p = 0; p < 8; p++) {
            int q = tid + 256 * p;            // 2048 float4 per tile
            int r = q >> 4, d4 = (q & 15) << 2;
            float4 vv = xg[q];
            ull* dst = sX + r * PADX + d4;
            dst[0] = pack2(vv.x * vv.x, vv.x);
            dst[1] = pack2(vv.y * vv.y, vv.y);
            dst[2] = pack2(vv.z * vv.z, vv.z);
            dst[3] = pack2(vv.w * vv.w, vv.w);
        }
        __syncthreads();

        ull acc[8][8];
        #pragma unroll
        for (int i = 0; i < 8; i++)
            #pragma unroll
            for (int j = 0; j < 8; j++) acc[i][j] = 0ULL;

        const ull* xrow = sX + (ty * 8) * PADX;
        #pragma unroll 2
        for (int kp = 0; kp < DD / 2; kp++) {
            ulonglong2 xv[8];
            #pragma unroll
            for (int i = 0; i < 8; i++)
                xv[i] = *(const ulonglong2*)&xrow[i * PADX + 2 * kp];
            const ull* wrow = sW + kp * (2 * KK) + tx * 2;
            #pragma unroll
            for (int j = 0; j < 8; j++) {
                ulonglong2 wv = *(const ulonglong2*)&wrow[j * 32];
                #pragma unroll
                for (int i = 0; i < 8; i++) {
                    ffma2(acc[i][j], wv.x, xv[i].x);
                    ffma2(acc[i][j], wv.y, xv[i].y);
                }
            }
        }

        // fused softmax epilogue: row owned by 16 lanes sharing ty
        #pragma unroll
        for (int i = 0; i < 8; i++) {
            int row = ty * 8 + i;
            float lg[8];
            float m = -3.402823466e+38f;
            #pragma unroll
            for (int j = 0; j < 8; j++) {
                ull a = acc[i][j];
                float lo = __uint_as_float((unsigned)a);
                float hi = __uint_as_float((unsigned)(a >> 32));
                lg[j] = lo + hi + sA[tx + 16 * j];
                m = fmaxf(m, lg[j]);
            }
            #pragma unroll
            for (int o = 8; o > 0; o >>= 1)
                m = fmaxf(m, __shfl_xor_sync(0xffffffffu, m, o));
            float s = 0.f;
            #pragma unroll
            for (int j = 0; j < 8; j++) { lg[j] = __expf(lg[j] - m); s += lg[j]; }
            #pragma unroll
            for (int o = 8; o > 0; o >>= 1)
                s += __shfl_xor_sync(0xffffffffu, s, o);
            float inv = 1.0f / s;
            float* orow = out + (size_t)(rowbase + row) * KK;
            #pragma unroll
            for (int j = 0; j < 8; j++) orow[tx + 16 * j] = lg[j] * inv;
            if (tx == 0) llacc += (double)(m + logf(s));
        }
    }

    // one atomic per block
    if (tx == 0) dll[ty] = llacc;
    __syncthreads();
    if (tid == 0) {
        double t = 0.0;
        #pragma unroll
        for (int i = 0; i < 16; i++) t += dll[i];
        atomicAdd(&g_ll, t);
    }
}

// ---------------------------------------------------------------- finalize
__global__ void fin_kernel(float* out, long long idx) {
    out[idx] = (float)(g_kl - g_ll);
}

// ---------------------------------------------------------------- launch
extern "C" void kernel_launch(void* const* d_in, const int* in_sizes, int n_in,
                              void* d_out, int out_size) {
    const float* x    = (const float*)d_in[0];
    const float* nu   = (const float*)d_in[1];
    const float* nv   = (const float*)d_in[2];
    const float* ntau = (const float*)d_in[3];
    const float* nc   = (const float*)d_in[4];
    const float* nn   = (const float*)d_in[5];
    const float* nB   = (const float*)d_in[6];

    int K = in_sizes[1];
    int D = in_sizes[3] / K;
    int N = in_sizes[0] / D;
    int ntiles = N / BM;

    size_t smbytes = (size_t)(DD * KK + BM * PADX) * 8 + KK * 4 + 16 * 8;
    cudaFuncSetAttribute(main_kernel, cudaFuncAttributeMaxDynamicSharedMemorySize,
                         (int)smbytes);

    setup1_kernel<<<KK, DD>>>(nu, nv, ntau, nc, nn, nB);
    setup2_kernel<<<1, KK>>>();
    main_kernel<<<GRID_MAIN, 256, smbytes>>>(x, (float*)d_out, ntiles);
    fin_kernel<<<1, 1>>>((float*)d_out, (long long)out_size - 1);
}

// round 3
// speedup vs baseline: 2.2060x; 1.1005x over previous
#include <cuda_runtime.h>
#include <math.h>
#include <stdint.h>

#define KK 128
#define DD 64
#define BM 128
#define PADX 66                 // ull stride per sX row (even -> 16B-aligned pairs)
#define LOG2PI 1.8378770664093454835
#define NTHREADS 512

typedef unsigned long long ull;

// weights packed (w2=-0.5*nb, w1=tau*nb), pair layout [kp=d/2][k][d&1]
__device__ ull    g_wcomb[DD * KK];
__device__ float  g_A[KK];
__device__ double g_kl;
__device__ double g_ll;
__device__ unsigned g_cnt;
__device__ double g_estick[KK], g_e1m[KK], g_base[KK], g_klk[KK];

// ---------------------------------------------------------------- helpers
__device__ __forceinline__ ull pack2(float lo, float hi) {
    return (ull)__float_as_uint(lo) | ((ull)__float_as_uint(hi) << 32);
}

__device__ __forceinline__ void ffma2(ull& acc, ull a, ull b) {
    asm("fma.rn.f32x2 %0, %1, %2, %3;" : "=l"(acc) : "l"(a), "l"(b), "l"(acc));
}

__device__ double dg(double x) {   // digamma, double precision
    double s = 0.0;
    while (x < 8.0) { s -= 1.0 / x; x += 1.0; }
    double inv = 1.0 / x, i2 = inv * inv;
    double r = log(x) - 0.5 * inv
        - i2 * (1.0/12.0 - i2 * (1.0/120.0 - i2 * (1.0/252.0
          - i2 * (1.0/240.0 - i2 * (1.0/132.0)))));
    return r + s;
}

// ---------------------------------------------------------------- setup, stage 1
// one block per k (128 blocks), one thread per d (64 threads)
__global__ void setup1_kernel(const float* __restrict__ nu, const float* __restrict__ nv,
                              const float* __restrict__ ntau, const float* __restrict__ nc,
                              const float* __restrict__ nn, const float* __restrict__ nB) {
    __shared__ double sred[3][2];
    int k = blockIdx.x, d = threadIdx.x;
    int lane = d & 31, warp = d >> 5;

    double c = (double)nc[k];
    double n = (double)nn[k] - (double)DD - 2.0;

    double t   = (double)ntau[k * DD + d] / c;
    double B   = (double)nB[k * DD + d] - c * t * t;
    double nbv = n / B;
    g_wcomb[(d >> 1) * (2 * KK) + (k << 1) + (d & 1)]
        = pack2((float)(-0.5 * nbv), (float)(t * nbv));

    double logb1 = log(0.5 * B);
    double t2nb  = t * t * nbv;
    double rat   = (0.5 - 0.5 * B) / (0.5 * B);   // (b0g - b1)/b1, b0g = 0.5

    #pragma unroll
    for (int off = 16; off > 0; off >>= 1) {
        logb1 += __shfl_down_sync(0xffffffffu, logb1, off);
        t2nb  += __shfl_down_sync(0xffffffffu, t2nb,  off);
        rat   += __shfl_down_sync(0xffffffffu, rat,   off);
    }
    if (lane == 0) { sred[0][warp] = logb1; sred[1][warp] = t2nb; sred[2][warp] = rat; }
    __syncthreads();

    if (d == 0) {
        double SlogB = sred[0][0] + sred[0][1];
        double St2   = sred[1][0] + sred[1][1];
        double Srat  = sred[2][0] + sred[2][1];

        double a1 = 0.5 * n, a0g = 0.5 * ((double)DD + 2.0), b0g = 0.5;
        double dga1 = dg(a1), lga1 = lgamma(a1), lga0g = lgamma(a0g);

        double e_log_det = (double)DD * dga1 - SlogB;
        double klg = (double)DD * ((a1 - a0g) * dga1 - lga1 + lga0g - a0g * log(b0g))
                   + a0g * SlogB + a1 * Srat;
        double kln = 0.5 * ((double)DD * (log(c) + 1.0 / c - 1.0) + St2);

        double u = (double)nu[k] + 1.0, v = (double)nv[k] + 1.0;
        double dgu = dg(u), dgv = dg(v), dguv = dg(u + v);
        double klb = lgamma(u + v) - lgamma(u) - lgamma(v)
                   + (u - 1.0) * dgu + (v - 1.0) * dgv + (2.0 - u - v) * dguv;

        g_estick[k] = dgu - dguv;
        g_e1m[k]    = dgv - dguv;
        g_base[k]   = 0.5 * (e_log_det - (double)DD * LOG2PI - St2 - (double)DD / c);
        g_klk[k]    = klb + klg + kln;
    }
}

// ---------------------------------------------------------------- setup, stage 2
__global__ void setup2_kernel() {
    __shared__ double sh[KK], pre[KK], red[KK];
    int k = threadIdx.x;
    sh[k]  = g_e1m[k];
    red[k] = g_klk[k];
    __syncthreads();
    if (k == 0) {
        double a = 0.0;
        for (int j = 0; j < KK; j++) { pre[j] = a; a += sh[j]; }
    }
    __syncthreads();
    g_A[k] = (float)(g_estick[k] + pre[k] + g_base[k]);
    __syncthreads();
    for (int off = KK / 2; off > 0; off >>= 1) {
        if (k < off) red[k] += red[k + off];
        __syncthreads();
    }
    if (k == 0) { g_kl = red[0]; g_ll = 0.0; g_cnt = 0; }
}

// ---------------------------------------------------------------- main GEMM+softmax
__global__ void __launch_bounds__(NTHREADS, 1)
main_kernel(const float* __restrict__ x, float* __restrict__ out, int ntiles,
            long long outidx) {
    extern __shared__ ull smem[];
    ull*    sW  = smem;                        // [32][128][2] packed weight pairs
    ull*    sX  = smem + DD * KK;              // [BM][PADX] packed (x^2, x)
    float*  sA  = (float*)(smem + DD * KK + BM * PADX);
    double* dll = (double*)(sA + KK);

    int tid = threadIdx.x;
    int tx = tid & 31, ty = tid >> 5;          // warp ty owns rows ty*8..ty*8+7

    // stage weights + A once per block
    #pragma unroll
    for (int i = tid; i < DD * KK; i += NTHREADS) sW[i] = g_wcomb[i];
    if (tid < KK) sA[tid] = g_A[tid];

    double llacc = 0.0;

    for (int tile = blockIdx.x; tile < ntiles; tile += gridDim.x) {
        __syncthreads();   // protect sX (prev readers) / sW staging (first iter)

        int rowbase = tile * BM;
        const float4* xg = (const float4*)(x + (size_t)rowbase * DD);
        #pragma unroll
        for (int p = 0; p < 4; p++) {
            int q = tid + NTHREADS * p;        // 2048 float4 per tile
            int r = q >> 4, d4 = (q & 15) << 2;
            float4 vv = xg[q];
            ull* dst = sX + r * PADX + d4;
            dst[0] = pack2(vv.x * vv.x, vv.x);
            dst[1] = pack2(vv.y * vv.y, vv.y);
            dst[2] = pack2(vv.z * vv.z, vv.z);
            dst[3] = pack2(vv.w * vv.w, vv.w);
        }
        __syncthreads();

        ull acc[8][4];
        #pragma unroll
        for (int i = 0; i < 8; i++)
            #pragma unroll
            for (int j = 0; j < 4; j++) acc[i][j] = 0ULL;

        const ull* xrow = sX + (ty * 8) * PADX;
        #pragma unroll 2
        for (int kp = 0; kp < DD / 2; kp++) {
            ulonglong2 wv[4];
            const ull* wrow = sW + kp * (2 * KK) + tx * 2;
            #pragma unroll
            for (int j = 0; j < 4; j++)
                wv[j] = *(const ulonglong2*)&wrow[j * 64];
            #pragma unroll
            for (int i = 0; i < 8; i++) {
                ulonglong2 xv = *(const ulonglong2*)&xrow[i * PADX + 2 * kp];
                #pragma unroll
                for (int j = 0; j < 4; j++) ffma2(acc[i][j], wv[j].x, xv.x);
                #pragma unroll
                for (int j = 0; j < 4; j++) ffma2(acc[i][j], wv[j].y, xv.y);
            }
        }

        // fused softmax: row ty*8+i fully owned by warp ty (32 lanes x 4 cols)
        #pragma unroll
        for (int i = 0; i < 8; i++) {
            int row = ty * 8 + i;
            float lg[4];
            float m = -3.402823466e+38f;
            #pragma unroll
            for (int j = 0; j < 4; j++) {
                ull a = acc[i][j];
                float lo = __uint_as_float((unsigned)a);
                float hi = __uint_as_float((unsigned)(a >> 32));
                lg[j] = lo + hi + sA[tx + 32 * j];
                m = fmaxf(m, lg[j]);
            }
            #pragma unroll
            for (int o = 16; o > 0; o >>= 1)
                m = fmaxf(m, __shfl_xor_sync(0xffffffffu, m, o));
            float s = 0.f;
            #pragma unroll
            for (int j = 0; j < 4; j++) { lg[j] = __expf(lg[j] - m); s += lg[j]; }
            #pragma unroll
            for (int o = 16; o > 0; o >>= 1)
                s += __shfl_xor_sync(0xffffffffu, s, o);
            float inv = 1.0f / s;
            float* orow = out + (size_t)(rowbase + row) * KK;
            #pragma unroll
            for (int j = 0; j < 4; j++) orow[tx + 32 * j] = lg[j] * inv;
            if (tx == 0) llacc += (double)(m + logf(s));
        }
    }

    if (tx == 0) dll[ty] = llacc;
    __syncthreads();
    if (tid == 0) {
        double t = 0.0;
        #pragma unroll
        for (int i = 0; i < 16; i++) t += dll[i];
        atomicAdd(&g_ll, t);
        __threadfence();
        unsigned old = atomicAdd(&g_cnt, 1u);
        if (old == gridDim.x - 1) {             // last block finalizes
            __threadfence();
            double ll = *((volatile double*)&g_ll);
            out[outidx] = (float)(g_kl - ll);
        }
    }
}

// ---------------------------------------------------------------- launch
extern "C" void kernel_launch(void* const* d_in, const int* in_sizes, int n_in,
                              void* d_out, int out_size) {
    const float* x    = (const float*)d_in[0];
    const float* nu   = (const float*)d_in[1];
    const float* nv   = (const float*)d_in[2];
    const float* ntau = (const float*)d_in[3];
    const float* nc   = (const float*)d_in[4];
    const float* nn   = (const float*)d_in[5];
    const float* nB   = (const float*)d_in[6];

    int K = in_sizes[1];
    int D = in_sizes[3] / K;
    int N = in_sizes[0] / D;
    int ntiles = N / BM;
    int grid = ntiles < 148 ? ntiles : 148;

    size_t smbytes = (size_t)(DD * KK + BM * PADX) * 8 + KK * 4 + 16 * 8;
    cudaFuncSetAttribute(main_kernel, cudaFuncAttributeMaxDynamicSharedMemorySize,
                         (int)smbytes);

    setup1_kernel<<<KK, DD>>>(nu, nv, ntau, nc, nn, nB);
    setup2_kernel<<<1, KK>>>();
    main_kernel<<<grid, NTHREADS, smbytes>>>(x, (float*)d_out, ntiles,
                                             (long long)out_size - 1);
}

// round 4
// speedup vs baseline: 2.3999x; 1.0879x over previous
#include <cuda_runtime.h>
#include <math.h>
#include <stdint.h>

#define KK 128
#define DD 64
#define BM 128
#define PADX 66                 // ull stride per sX row (even -> 16B-aligned pairs)
#define LOG2PI 1.8378770664093454835
#define NTHREADS 512

typedef unsigned long long ull;

// weights packed (w2=-0.5*nb, w1=tau*nb), pair layout [kp=d/2][k][d&1]
__device__ ull    g_wcomb[DD * KK];
__device__ float  g_A[KK];
__device__ double g_kl;
__device__ double g_ll;
__device__ unsigned g_cnt;
__device__ double g_estick[KK], g_e1m[KK], g_base[KK], g_klk[KK];

// ---------------------------------------------------------------- helpers
__device__ __forceinline__ ull pack2(float lo, float hi) {
    return (ull)__float_as_uint(lo) | ((ull)__float_as_uint(hi) << 32);
}

__device__ __forceinline__ void ffma2(ull& acc, ull a, ull b) {
    asm("fma.rn.f32x2 %0, %1, %2, %3;" : "=l"(acc) : "l"(a), "l"(b), "l"(acc));
}

__device__ float dgf(float x) {    // digamma, float (err ~1e-7 abs)
    float s = 0.0f;
    while (x < 8.0f) { s -= 1.0f / x; x += 1.0f; }
    float inv = 1.0f / x, i2 = inv * inv;
    float r = logf(x) - 0.5f * inv
        - i2 * (8.3333333e-2f - i2 * (8.3333333e-3f - i2 * (3.9682540e-3f
          - i2 * (4.1666667e-3f - i2 * 7.5757576e-3f))));
    return r + s;
}

// ---------------------------------------------------------------- setup, stage 1
// one block per k (128 blocks), one thread per d (64 threads); float specials
__global__ void setup1_kernel(const float* __restrict__ nu, const float* __restrict__ nv,
                              const float* __restrict__ ntau, const float* __restrict__ nc,
                              const float* __restrict__ nn, const float* __restrict__ nB) {
    __shared__ double sred[3][2];
    int k = blockIdx.x, d = threadIdx.x;
    int lane = d & 31, warp = d >> 5;

    float c = nc[k];
    float n = nn[k] - (float)DD - 2.0f;

    float t   = ntau[k * DD + d] / c;
    float B   = nB[k * DD + d] - c * t * t;
    float nbv = n / B;
    g_wcomb[(d >> 1) * (2 * KK) + (k << 1) + (d & 1)]
        = pack2(-0.5f * nbv, t * nbv);

    double logb1 = (double)logf(0.5f * B);
    double t2nb  = (double)(t * t * nbv);
    double rat   = (double)((0.5f - 0.5f * B) / (0.5f * B));   // (b0g-b1)/b1, b0g=0.5

    #pragma unroll
    for (int off = 16; off > 0; off >>= 1) {
        logb1 += __shfl_down_sync(0xffffffffu, logb1, off);
        t2nb  += __shfl_down_sync(0xffffffffu, t2nb,  off);
        rat   += __shfl_down_sync(0xffffffffu, rat,   off);
    }
    if (lane == 0) { sred[0][warp] = logb1; sred[1][warp] = t2nb; sred[2][warp] = rat; }
    __syncthreads();

    if (d == 0) {
        double SlogB = sred[0][0] + sred[0][1];
        double St2   = sred[1][0] + sred[1][1];
        double Srat  = sred[2][0] + sred[2][1];

        float  a1f = 0.5f * n;
        double a1 = (double)a1f, a0g = 0.5 * ((double)DD + 2.0), b0g = 0.5;
        double dga1 = (double)dgf(a1f);
        double lga1 = (double)lgammaf(a1f);
        double lga0g = (double)lgammaf((float)a0g);

        double e_log_det = (double)DD * dga1 - SlogB;
        double klg = (double)DD * ((a1 - a0g) * dga1 - lga1 + lga0g - a0g * log(b0g))
                   + a0g * SlogB + a1 * Srat;
        double kln = 0.5 * ((double)DD * ((double)logf(c) + 1.0 / (double)c - 1.0) + St2);

        float u = nu[k] + 1.0f, v = nv[k] + 1.0f;
        double dgu = (double)dgf(u), dgv = (double)dgf(v), dguv = (double)dgf(u + v);
        double klb = (double)lgammaf(u + v) - (double)lgammaf(u) - (double)lgammaf(v)
                   + ((double)u - 1.0) * dgu + ((double)v - 1.0) * dgv
                   + (2.0 - (double)u - (double)v) * dguv;

        g_estick[k] = dgu - dguv;
        g_e1m[k]    = dgv - dguv;
        g_base[k]   = 0.5 * (e_log_det - (double)DD * LOG2PI - St2
                             - (double)DD / (double)c);
        g_klk[k]    = klb + klg + kln;
    }
}

// ---------------------------------------------------------------- setup, stage 2
__global__ void setup2_kernel() {
    __shared__ double sh[KK], pre[KK], red[KK];
    int k = threadIdx.x;
    sh[k]  = g_e1m[k];
    red[k] = g_klk[k];
    __syncthreads();
    if (k == 0) {
        double a = 0.0;
        for (int j = 0; j < KK; j++) { pre[j] = a; a += sh[j]; }
    }
    __syncthreads();
    g_A[k] = (float)(g_estick[k] + pre[k] + g_base[k]);
    __syncthreads();
    for (int off = KK / 2; off > 0; off >>= 1) {
        if (k < off) red[k] += red[k + off];
        __syncthreads();
    }
    if (k == 0) { g_kl = red[0]; g_ll = 0.0; g_cnt = 0; }
}

// ---------------------------------------------------------------- main GEMM+softmax
__global__ void __launch_bounds__(NTHREADS, 1)
main_kernel(const float* __restrict__ x, float* __restrict__ out, int ntiles,
            long long outidx) {
    extern __shared__ ull smem[];
    ull*    sW  = smem;                           // [32][128][2] weight pairs
    ull*    sX0 = smem + DD * KK;                 // double-buffered x tiles
    ull*    sX1 = sX0 + BM * PADX;
    float*  sA  = (float*)(sX1 + BM * PADX);
    double* dll = (double*)(sA + KK);

    int tid = threadIdx.x;
    int tx = tid & 31, ty = tid >> 5;             // warp ty owns rows ty*8..+7

    // stage weights + A once per block
    #pragma unroll
    for (int i = tid; i < DD * KK; i += NTHREADS) sW[i] = g_wcomb[i];
    if (tid < KK) sA[tid] = g_A[tid];

    // stage first tile into buffer 0
    int tile = blockIdx.x;
    if (tile < ntiles) {
        const float4* xg = (const float4*)(x + (size_t)tile * BM * DD);
        #pragma unroll
        for (int p = 0; p < 4; p++) {
            int q = tid + NTHREADS * p;
            int r = q >> 4, d4 = (q & 15) << 2;
            float4 vv = xg[q];
            ull* dst = sX0 + r * PADX + d4;
            dst[0] = pack2(vv.x * vv.x, vv.x);
            dst[1] = pack2(vv.y * vv.y, vv.y);
            dst[2] = pack2(vv.z * vv.z, vv.z);
            dst[3] = pack2(vv.w * vv.w, vv.w);
        }
    }
    __syncthreads();

    // hoist per-thread softmax constants
    float aj[4];
    #pragma unroll
    for (int j = 0; j < 4; j++) aj[j] = sA[tx + 32 * j];

    double llacc = 0.0;
    int p = 0;

    for (; tile < ntiles; tile += gridDim.x) {
        ull* sX = p ? sX1 : sX0;

        ull acc[8][4];
        #pragma unroll
        for (int i = 0; i < 8; i++)
            #pragma unroll
            for (int j = 0; j < 4; j++) acc[i][j] = 0ULL;

        const ull* xrow = sX + (ty * 8) * PADX;
        #pragma unroll 2
        for (int kp = 0; kp < DD / 2; kp++) {
            ulonglong2 wv[4];
            const ull* wrow = sW + kp * (2 * KK) + tx * 2;
            #pragma unroll
            for (int j = 0; j < 4; j++)
                wv[j] = *(const ulonglong2*)&wrow[j * 64];
            #pragma unroll
            for (int i = 0; i < 8; i++) {
                ulonglong2 xv = *(const ulonglong2*)&xrow[i * PADX + 2 * kp];
                #pragma unroll
                for (int j = 0; j < 4; j++) ffma2(acc[i][j], wv[j].x, xv.x);
                #pragma unroll
                for (int j = 0; j < 4; j++) ffma2(acc[i][j], wv[j].y, xv.y);
            }
        }

        // fused softmax: row ty*8+i fully owned by warp ty (32 lanes x 4 cols)
        int rowbase = tile * BM;
        #pragma unroll
        for (int i = 0; i < 8; i++) {
            int row = ty * 8 + i;
            float lg[4];
            float m = -3.402823466e+38f;
            #pragma unroll
            for (int j = 0; j < 4; j++) {
                ull a = acc[i][j];
                float lo = __uint_as_float((unsigned)a);
                float hi = __uint_as_float((unsigned)(a >> 32));
                lg[j] = lo + hi + aj[j];
                m = fmaxf(m, lg[j]);
            }
            #pragma unroll
            for (int o = 16; o > 0; o >>= 1)
                m = fmaxf(m, __shfl_xor_sync(0xffffffffu, m, o));
            float s = 0.f;
            #pragma unroll
            for (int j = 0; j < 4; j++) { lg[j] = __expf(lg[j] - m); s += lg[j]; }
            #pragma unroll
            for (int o = 16; o > 0; o >>= 1)
                s += __shfl_xor_sync(0xffffffffu, s, o);
            float inv = 1.0f / s;
            float* orow = out + (size_t)(rowbase + row) * KK;
            #pragma unroll
            for (int j = 0; j < 4; j++) orow[tx + 32 * j] = lg[j] * inv;
            if (tx == 0) llacc += (double)(m + __logf(s));
        }

        // stage next tile into the other buffer (overlaps epilogue drain)
        int nxt = tile + gridDim.x;
        if (nxt < ntiles) {
            ull* sN = p ? sX0 : sX1;
            const float4* xg = (const float4*)(x + (size_t)nxt * BM * DD);
            #pragma unroll
            for (int q4 = 0; q4 < 4; q4++) {
                int q = tid + NTHREADS * q4;
                int r = q >> 4, d4 = (q & 15) << 2;
                float4 vv = xg[q];
                ull* dst = sN + r * PADX + d4;
                dst[0] = pack2(vv.x * vv.x, vv.x);
                dst[1] = pack2(vv.y * vv.y, vv.y);
                dst[2] = pack2(vv.z * vv.z, vv.z);
                dst[3] = pack2(vv.w * vv.w, vv.w);
            }
        }
        __syncthreads();
        p ^= 1;
    }

    if (tx == 0) dll[ty] = llacc;
    __syncthreads();
    if (tid == 0) {
        double t = 0.0;
        #pragma unroll
        for (int i = 0; i < 16; i++) t += dll[i];
        atomicAdd(&g_ll, t);
        __threadfence();
        unsigned old = atomicAdd(&g_cnt, 1u);
        if (old == gridDim.x - 1) {             // last block finalizes
            __threadfence();
            double ll = *((volatile double*)&g_ll);
            out[outidx] = (float)(g_kl - ll);
        }
    }
}

// ---------------------------------------------------------------- launch
extern "C" void kernel_launch(void* const* d_in, const int* in_sizes, int n_in,
                              void* d_out, int out_size) {
    const float* x    = (const float*)d_in[0];
    const float* nu   = (const float*)d_in[1];
    const float* nv   = (const float*)d_in[2];
    const float* ntau = (const float*)d_in[3];
    const float* nc   = (const float*)d_in[4];
    const float* nn   = (const float*)d_in[5];
    const float* nB   = (const float*)d_in[6];

    int K = in_sizes[1];
    int D = in_sizes[3] / K;
    int N = in_sizes[0] / D;
    int ntiles = N / BM;
    int grid = ntiles < 148 ? ntiles : 148;

    size_t smbytes = (size_t)(DD * KK + 2 * BM * PADX) * 8 + KK * 4 + 16 * 8;
    cudaFuncSetAttribute(main_kernel, cudaFuncAttributeMaxDynamicSharedMemorySize,
                         (int)smbytes);

    setup1_kernel<<<KK, DD>>>(nu, nv, ntau, nc, nn, nB);
    setup2_kernel<<<1, KK>>>();
    main_kernel<<<grid, NTHREADS, smbytes>>>(x, (float*)d_out, ntiles,
                                             (long long)out_size - 1);
}